// round 4
// baseline (speedup 1.0000x reference)
#include <cuda_runtime.h>
#include <math_constants.h>

#define NEXP 64
#define HID 128
#define TOPK 6
#define TPB 128
#define TOK_PER_BLK 256   // 2 tokens per thread

__device__ float        g_ssum[NEXP];
__device__ unsigned int g_cnt[NEXP];

__device__ __forceinline__ unsigned long long pack2(float lo, float hi) {
    unsigned long long r;
    asm("mov.b64 %0, {%1,%2};" : "=l"(r) : "f"(lo), "f"(hi));
    return r;
}
__device__ __forceinline__ void unpack2(unsigned long long v, float& lo, float& hi) {
    asm("mov.b64 {%0,%1}, %2;" : "=f"(lo), "=f"(hi) : "l"(v));
}
// d = a*b + d  (two packed fp32 FMAs, exact same rounding as scalar fmaf)
__device__ __forceinline__ void fma2(unsigned long long& d, unsigned long long a, unsigned long long b) {
    asm("fma.rn.f32x2 %0, %1, %2, %0;" : "+l"(d) : "l"(a), "l"(b));
}

__global__ __launch_bounds__(TPB)
void gate_kernel(const float* __restrict__ X, const float* __restrict__ W,
                 float* __restrict__ out, int N)
{
    // W staged as expert-PAIRS per k:  Wsh[k][j] = { W[2j][k], W[2j+1][k] }
    __shared__ float2       Wsh[HID][NEXP / 2];   // 32 KB
    __shared__ float        Ssh[NEXP];            // block softmax-score sums (for Pi)
    __shared__ unsigned int Hsh[NEXP];            // block top-k histogram (for ce)

    const int tid = threadIdx.x;

    for (int i = tid; i < HID * (NEXP / 2); i += TPB) {
        int k = i >> 5;
        int j = i & 31;
        Wsh[k][j] = make_float2(W[(2 * j) * HID + k], W[(2 * j + 1) * HID + k]);
    }
    if (tid < NEXP) { Ssh[tid] = 0.f; Hsh[tid] = 0u; }
    __syncthreads();

    const int t0 = blockIdx.x * TOK_PER_BLK + tid;
    const int t1 = t0 + TPB;

    unsigned long long accA[32], accB[32];
#pragma unroll
    for (int j = 0; j < 32; j++) { accA[j] = 0ull; accB[j] = 0ull; }

    const float4* __restrict__ xa = reinterpret_cast<const float4*>(X + (size_t)t0 * HID);
    const float4* __restrict__ xb = reinterpret_cast<const float4*>(X + (size_t)t1 * HID);

    float4 a4 = xa[0];
    float4 b4 = xb[0];

#pragma unroll 1
    for (int k4 = 0; k4 < HID / 4; k4++) {
        // prefetch next x quad (clamped on last iter; value unused then)
        int nxt = (k4 + 1 < HID / 4) ? (k4 + 1) : k4;
        float4 na = xa[nxt];
        float4 nb = xb[nxt];

        float ax[4] = { a4.x, a4.y, a4.z, a4.w };
        float bx[4] = { b4.x, b4.y, b4.z, b4.w };
#pragma unroll
        for (int kk = 0; kk < 4; kk++) {
            int k = 4 * k4 + kk;
            unsigned long long a2 = pack2(ax[kk], ax[kk]);
            unsigned long long b2 = pack2(bx[kk], bx[kk]);
            const unsigned long long* wr =
                reinterpret_cast<const unsigned long long*>(&Wsh[k][0]);
#pragma unroll
            for (int j = 0; j < 32; j++) {
                unsigned long long w = wr[j];   // LDS.64 broadcast (uniform addr)
                fma2(accA[j], a2, w);
                fma2(accB[j], b2, w);
            }
        }
        a4 = na; b4 = nb;
    }

    // -------- epilogue: one token at a time (code emitted once; tt dynamic) -----
#pragma unroll 1
    for (int tt = 0; tt < 2; tt++) {
        const int t = tt ? t1 : t0;

        float v[NEXP];
#pragma unroll
        for (int j = 0; j < 32; j++) {
            unsigned long long a = tt ? accB[j] : accA[j];
            unpack2(a, v[2 * j], v[2 * j + 1]);
        }

        // stable top-6: strict-> ascending scan + (value,index) ordering vs previous pick
        // matches jax.lax.top_k (ties -> lower index first), no value destruction.
        float pv = CUDART_INF_F;
        int   pi = -1;
        float bvals[TOPK];
        float m = 0.f;
#pragma unroll 1
        for (int p = 0; p < TOPK; p++) {
            float best = -CUDART_INF_F;
            int   bi   = -1;
#pragma unroll
            for (int e = 0; e < NEXP; e++) {
                bool elig = (v[e] < pv) || ((v[e] == pv) && (e > pi));
                if (elig && (v[e] > best)) { best = v[e]; bi = e; }
            }
            pv = best; pi = bi;
            bvals[p] = best;
            if (p == 0) m = best;
            out[(size_t)t * TOPK + p] = (float)bi;     // idx as float
            atomicAdd(&Hsh[bi], 1u);
        }

        // softmax denominator (4-way partial sums to break the FADD chain)
        float d0 = 0.f, d1 = 0.f, d2 = 0.f, d3 = 0.f;
#pragma unroll
        for (int e = 0; e < NEXP; e += 4) {
            v[e]     = __expf(v[e]     - m); d0 += v[e];
            v[e + 1] = __expf(v[e + 1] - m); d1 += v[e + 1];
            v[e + 2] = __expf(v[e + 2] - m); d2 += v[e + 2];
            v[e + 3] = __expf(v[e + 3] - m); d3 += v[e + 3];
        }
        float denom = (d0 + d1) + (d2 + d3);
        float invd  = 1.0f / denom;

        // Pi accumulation: per-expert softmax scores into block shared
#pragma unroll
        for (int e = 0; e < NEXP; e++) atomicAdd(&Ssh[e], v[e] * invd);

        // normalized top-k weights
        float sw[TOPK];
        float tsum = 0.f;
#pragma unroll 1
        for (int p = 0; p < TOPK; p++) {
            float s = __expf(bvals[p] - m) * invd;   // == score of that expert
            sw[p] = s;
            tsum += s;
        }
        float tinv = 1.0f / (tsum + 1e-20f);
#pragma unroll 1
        for (int p = 0; p < TOPK; p++) {
            out[(size_t)N * TOPK + (size_t)t * TOPK + p] = sw[p] * tinv;
        }
    }

    __syncthreads();
    if (tid < NEXP) {
        atomicAdd(&g_ssum[tid], Ssh[tid]);
        atomicAdd(&g_cnt[tid], Hsh[tid]);
    }
}

__global__ void zero_kernel() {
    int i = threadIdx.x;
    if (i < NEXP) { g_ssum[i] = 0.f; g_cnt[i] = 0u; }
}

__global__ void aux_kernel(float* __restrict__ out, int N) {
    __shared__ float red[NEXP];
    int e = threadIdx.x;
    float Pi = g_ssum[e] / (float)N;
    float ce = (float)g_cnt[e] / ((float)N * (float)TOPK);
    float fi = ce * (float)NEXP;
    red[e] = Pi * fi;
    __syncthreads();
    if (e == 0) {
        float s = 0.f;
        for (int j = 0; j < NEXP; j++) s += red[j];
        out[(size_t)N * TOPK * 2] = s * 1e-3f;   // ALPHA
    }
}

extern "C" void kernel_launch(void* const* d_in, const int* in_sizes, int n_in,
                              void* d_out, int out_size)
{
    const float* X = (const float*)d_in[0];   // (64,4096,128) fp32 -> (N,128)
    const float* W = (const float*)d_in[1];   // (64,128) fp32
    float* out = (float*)d_out;
    int N = in_sizes[0] / HID;                // 262144

    zero_kernel<<<1, 64>>>();
    gate_kernel<<<N / TOK_PER_BLK, TPB>>>(X, W, out, N);
    aux_kernel<<<1, 64>>>(out, N);
}

// round 7
// speedup vs baseline: 4.5403x; 4.5403x over previous
#include <cuda_runtime.h>
#include <math_constants.h>

#define NEXP 64
#define HID 128
#define TOPK 6
#define TPB 128

__device__ float        g_ssum[NEXP];
__device__ unsigned int g_cnt[NEXP];
__device__ unsigned int g_done;

__device__ __forceinline__ unsigned long long pack2(float lo, float hi) {
    unsigned long long r;
    asm("mov.b64 %0, {%1,%2};" : "=l"(r) : "f"(lo), "f"(hi));
    return r;
}
__device__ __forceinline__ void unpack2(unsigned long long v, float& lo, float& hi) {
    asm("mov.b64 {%0,%1}, %2;" : "=f"(lo), "=f"(hi) : "l"(v));
}
// d = a*b + d  (two packed fp32 FMAs, same rounding as scalar fmaf)
__device__ __forceinline__ void fma2(unsigned long long& d, unsigned long long a, unsigned long long b) {
    asm("fma.rn.f32x2 %0, %1, %2, %0;" : "+l"(d) : "l"(a), "l"(b));
}

__global__ __launch_bounds__(TPB)
void gate_kernel(const float* __restrict__ X, const float* __restrict__ W,
                 float* __restrict__ out, int N)
{
    // Union: W tile during mainloop, score-transpose scratch during epilogue.
    __shared__ union {
        float2 w[HID][NEXP / 2];   // w[k][j] = { W[2j][k], W[2j+1][k] }  (32 KB)
        float  t[NEXP][130];       // transpose scratch: padded rows       (33.3 KB)
    } sh;
    __shared__ unsigned int Hsh[NEXP];   // block top-k histogram
    __shared__ unsigned int s_last;

    const int tid = threadIdx.x;

    // stage W as expert-pairs per k (quad-aligned so rows read as LDS.128)
    for (int i = tid; i < HID * (NEXP / 2); i += TPB) {
        int k = i >> 5;
        int j = i & 31;
        sh.w[k][j] = make_float2(W[(2 * j) * HID + k], W[(2 * j + 1) * HID + k]);
    }
    if (tid < NEXP) Hsh[tid] = 0u;
    __syncthreads();

    const int t = blockIdx.x * TPB + tid;

    unsigned long long acc[32];
#pragma unroll
    for (int j = 0; j < 32; j++) acc[j] = 0ull;

    const float4* __restrict__ xp = reinterpret_cast<const float4*>(X + (size_t)t * HID);
    float4 a4 = xp[0];

#pragma unroll 1
    for (int k4 = 0; k4 < HID / 4; k4++) {
        int nxt = (k4 + 1 < HID / 4) ? (k4 + 1) : k4;
        float4 na = xp[nxt];                      // rolling prefetch (MLP=2)

        float ax[4] = { a4.x, a4.y, a4.z, a4.w };
#pragma unroll
        for (int kk = 0; kk < 4; kk++) {
            int k = 4 * k4 + kk;
            unsigned long long a2 = pack2(ax[kk], ax[kk]);
            const ulonglong2* wr = reinterpret_cast<const ulonglong2*>(&sh.w[k][0]);
#pragma unroll
            for (int j = 0; j < 16; j++) {        // 16x LDS.128 (broadcast), 32x FFMA2
                ulonglong2 w = wr[j];
                fma2(acc[2 * j],     a2, w.x);
                fma2(acc[2 * j + 1], a2, w.y);
            }
        }
        a4 = na;
    }

    // -------- epilogue (registers only; acc dies into v) --------
    float v[NEXP];
#pragma unroll
    for (int j = 0; j < 32; j++) unpack2(acc[j], v[2 * j], v[2 * j + 1]);

    // stable top-6: strict-descending scan with (value,index) tie order
    // (matches jax.lax.top_k: ties -> lower index first)
    float pv = CUDART_INF_F;
    int   pi = -1;
    float bvals[TOPK];
    float m = 0.f;
#pragma unroll 1
    for (int p = 0; p < TOPK; p++) {
        float best = -CUDART_INF_F;
        int   bi   = -1;
#pragma unroll
        for (int e = 0; e < NEXP; e++) {
            bool elig = (v[e] < pv) || ((v[e] == pv) && (e > pi));
            if (elig && (v[e] > best)) { best = v[e]; bi = e; }
        }
        pv = best; pi = bi;
        bvals[p] = best;
        if (p == 0) m = best;
        out[(size_t)t * TOPK + p] = (float)bi;    // idx as float
        atomicAdd(&Hsh[bi], 1u);
    }

    // softmax (4 partial sums break FADD chain)
    float d0 = 0.f, d1 = 0.f, d2 = 0.f, d3 = 0.f;
#pragma unroll
    for (int e = 0; e < NEXP; e += 4) {
        v[e]     = __expf(v[e]     - m); d0 += v[e];
        v[e + 1] = __expf(v[e + 1] - m); d1 += v[e + 1];
        v[e + 2] = __expf(v[e + 2] - m); d2 += v[e + 2];
        v[e + 3] = __expf(v[e + 3] - m); d3 += v[e + 3];
    }
    float invd = 1.0f / ((d0 + d1) + (d2 + d3));

    // normalized top-k weights
    {
        float sw[TOPK];
        float tsum = 0.f;
#pragma unroll 1
        for (int p = 0; p < TOPK; p++) {
            float s = __expf(bvals[p] - m) * invd;
            sw[p] = s;
            tsum += s;
        }
        float tinv = 1.0f / (tsum + 1e-20f);
#pragma unroll 1
        for (int p = 0; p < TOPK; p++)
            out[(size_t)N * TOPK + (size_t)t * TOPK + p] = sw[p] * tinv;
    }

    // scores for Pi
#pragma unroll
    for (int e = 0; e < NEXP; e++) v[e] *= invd;

    // -------- per-expert block score sums via smem transpose (no converged atomics)
    __syncthreads();                              // all mainloop reads of sh.w done
    const int col = tid + (tid >> 6);             // halves at cols [0,64) and [65,129)
#pragma unroll
    for (int e = 0; e < NEXP; e++) sh.t[e][col] = v[e];   // conflict-free STS
    __syncthreads();

    {
        int e = tid >> 1, h = tid & 1;
        int base = h * 65;
        float s0 = 0.f, s1 = 0.f, s2 = 0.f, s3 = 0.f;
#pragma unroll
        for (int i = 0; i < 64; i += 4) {
            s0 += sh.t[e][base + i];
            s1 += sh.t[e][base + i + 1];
            s2 += sh.t[e][base + i + 2];
            s3 += sh.t[e][base + i + 3];
        }
        float s = (s0 + s1) + (s2 + s3);
        s += __shfl_xor_sync(0xffffffffu, s, 1);  // combine the two halves
        if (h == 0) atomicAdd(&g_ssum[e], s);
    }
    if (tid < NEXP) atomicAdd(&g_cnt[tid], Hsh[tid]);

    // -------- last-block ticket: compute aux + reset globals for next replay
    __threadfence();
    __syncthreads();
    if (tid == 0) s_last = atomicAdd(&g_done, 1u);
    __syncthreads();
    if (s_last == gridDim.x - 1) {
        float* red = &sh.t[0][0];                 // reuse scratch (block-local)
        if (tid < NEXP) {
            float    ssum = atomicAdd(&g_ssum[tid], 0.0f);   // L2-coherent read
            unsigned cnt  = atomicAdd(&g_cnt[tid], 0u);
            float Pi = ssum / (float)N;
            float ce = (float)cnt / ((float)N * (float)TOPK);
            red[tid] = Pi * ce * (float)NEXP;
        }
        __syncthreads();
        if (tid == 0) {
            float s = 0.f;
            for (int j = 0; j < NEXP; j++) s += red[j];
            out[(size_t)N * TOPK * 2] = s * 1e-3f;           // ALPHA
        }
        if (tid < NEXP) { g_ssum[tid] = 0.f; g_cnt[tid] = 0u; }
        if (tid == 0) g_done = 0u;
    }
}

extern "C" void kernel_launch(void* const* d_in, const int* in_sizes, int n_in,
                              void* d_out, int out_size)
{
    const float* X = (const float*)d_in[0];   // (64,4096,128) fp32 -> (N,128)
    const float* W = (const float*)d_in[1];   // (64,128) fp32
    float* out = (float*)d_out;
    int N = in_sizes[0] / HID;                // 262144

    gate_kernel<<<N / TPB, TPB>>>(X, W, out, N);
}

// round 11
// speedup vs baseline: 5.7322x; 1.2625x over previous
#include <cuda_runtime.h>
#include <math_constants.h>

#define NEXP 64
#define HID 128
#define TOPK 6
#define TPB 128
#define CHUNK 8
#define NCHUNK (HID / CHUNK)   // 16
#define XROW 10                // 8 data + 2 pad words: 8B-aligned rows, <=2-way banks

__device__ float        g_ssum[NEXP];
__device__ unsigned int g_cnt[NEXP];
__device__ unsigned int g_done;

__device__ __forceinline__ unsigned long long pack2(float lo, float hi) {
    unsigned long long r;
    asm("mov.b64 %0, {%1,%2};" : "=l"(r) : "f"(lo), "f"(hi));
    return r;
}
// d = a*b + d  (two packed fp32 FMAs, same rounding as scalar fmaf)
__device__ __forceinline__ void fma2(unsigned long long& d, unsigned long long a, unsigned long long b) {
    asm("fma.rn.f32x2 %0, %1, %2, %0;" : "+l"(d) : "l"(a), "l"(b));
}

__global__ __launch_bounds__(TPB, 5)
void gate_kernel(const float* __restrict__ X, const float* __restrict__ W,
                 float* __restrict__ out, int N)
{
    // Union: {W tile + x double-buffer} during mainloop, score tile afterwards.
    __shared__ union {
        struct {
            float2 w[HID][NEXP / 2];   // w[k][j] = { W[2j][k], W[2j+1][k] }  (32 KB)
            float  x[2][TPB][XROW];    // x[buf][token][k-in-chunk]          (10 KB)
        } m;
        float t[TPB][70];              // scores [token][expert], pad 70     (35.8 KB)
    } sh;
    __shared__ unsigned int Hsh[NEXP];
    __shared__ unsigned int s_last;

    const int tid = threadIdx.x;
    const int p   = tid & 63;          // token slot: owns tokens p and p+64
    const int h   = tid >> 6;          // expert half: experts [32h, 32h+32)

    // stage W as expert-pairs per k (rows read as LDS.128 broadcast)
    for (int i = tid; i < HID * (NEXP / 2); i += TPB) {
        int k = i >> 5;
        int j = i & 31;
        sh.m.w[k][j] = make_float2(W[(2 * j) * HID + k], W[(2 * j + 1) * HID + k]);
    }
    if (tid < NEXP) Hsh[tid] = 0u;

    const size_t tokBase = (size_t)blockIdx.x * TPB;
    const float* __restrict__ xsrc = X + tokBase * HID;

    // ---- x staging: chunk c -> buffer b, 8B cp.async, 4 lanes per token row
    auto stage = [&](int c, int b) {
#pragma unroll
        for (int i = 0; i < 4; i++) {
            int o   = i * TPB + tid;
            int tok = o >> 2;
            int j   = o & 3;
            const float* src = xsrc + (size_t)tok * HID + c * CHUNK + j * 2;
            unsigned dst = (unsigned)__cvta_generic_to_shared(&sh.m.x[b][tok][j * 2]);
            asm volatile("cp.async.ca.shared.global [%0], [%1], 8;" :: "r"(dst), "l"(src));
        }
        asm volatile("cp.async.commit_group;");
    };

    stage(0, 0);
    asm volatile("cp.async.wait_group 0;");
    __syncthreads();                       // W + x chunk 0 visible

    unsigned long long accA[16], accB[16];
#pragma unroll
    for (int j = 0; j < 16; j++) { accA[j] = 0ull; accB[j] = 0ull; }

#pragma unroll 1
    for (int c = 0; c < NCHUNK; c++) {
        if (c + 1 < NCHUNK) stage(c + 1, (c + 1) & 1);

        const float (*xb)[XROW] = sh.m.x[c & 1];
#pragma unroll
        for (int kk = 0; kk < CHUNK; kk++) {
            int k = c * CHUNK + kk;
            float xa = xb[p][kk];
            float xc = xb[p + 64][kk];
            unsigned long long a2 = pack2(xa, xa);
            unsigned long long b2 = pack2(xc, xc);
            const ulonglong2* wr = reinterpret_cast<const ulonglong2*>(&sh.m.w[k][16 * h]);
#pragma unroll
            for (int j = 0; j < 8; j++) {          // 8x LDS.128 (uniform broadcast)
                ulonglong2 wv = wr[j];
                fma2(accA[2 * j],     a2, wv.x);
                fma2(accA[2 * j + 1], a2, wv.y);
                fma2(accB[2 * j],     b2, wv.x);
                fma2(accB[2 * j + 1], b2, wv.y);
            }
        }
        if (c + 1 < NCHUNK) asm volatile("cp.async.wait_group 0;");
        __syncthreads();                   // chunk ready; old buffer fully read
    }

    // -------- scores to tile: accA -> row p, accB -> row p+64, cols [32h, 32h+32)
#pragma unroll
    for (int j = 0; j < 16; j++) {
        *reinterpret_cast<unsigned long long*>(&sh.t[p][32 * h + 2 * j])      = accA[j];
        *reinterpret_cast<unsigned long long*>(&sh.t[p + 64][32 * h + 2 * j]) = accB[j];
    }
    __syncthreads();

    // -------- per-token epilogue: thread owns local token tid
    float v[NEXP];
#pragma unroll
    for (int i = 0; i < 32; i++) {
        float2 f = *reinterpret_cast<float2*>(&sh.t[tid][2 * i]);
        v[2 * i] = f.x; v[2 * i + 1] = f.y;
    }
    const size_t t = tokBase + tid;

    // stable top-6: strict-descending scan, (value,index) tie order
    // (matches jax.lax.top_k: ties -> lower index first)
    float pv = CUDART_INF_F;
    int   pi = -1;
    float bvals[TOPK];
    float m = 0.f;
#pragma unroll 1
    for (int q = 0; q < TOPK; q++) {
        float best = -CUDART_INF_F;
        int   bi   = -1;
#pragma unroll
        for (int e = 0; e < NEXP; e++) {
            bool elig = (v[e] < pv) || ((v[e] == pv) && (e > pi));
            if (elig && (v[e] > best)) { best = v[e]; bi = e; }
        }
        pv = best; pi = bi;
        bvals[q] = best;
        if (q == 0) m = best;
        out[t * TOPK + q] = (float)bi;     // idx as float
        atomicAdd(&Hsh[bi], 1u);
    }

    // softmax (4 partial sums break the FADD chain)
    float d0 = 0.f, d1 = 0.f, d2 = 0.f, d3 = 0.f;
#pragma unroll
    for (int e = 0; e < NEXP; e += 4) {
        v[e]     = __expf(v[e]     - m); d0 += v[e];
        v[e + 1] = __expf(v[e + 1] - m); d1 += v[e + 1];
        v[e + 2] = __expf(v[e + 2] - m); d2 += v[e + 2];
        v[e + 3] = __expf(v[e + 3] - m); d3 += v[e + 3];
    }
    float invd = 1.0f / ((d0 + d1) + (d2 + d3));

    // normalized top-k weights
    {
        float sw[TOPK];
        float tsum = 0.f;
#pragma unroll 1
        for (int q = 0; q < TOPK; q++) {
            float s = __expf(bvals[q] - m) * invd;
            sw[q] = s;
            tsum += s;
        }
        float tinv = 1.0f / (tsum + 1e-20f);
#pragma unroll 1
        for (int q = 0; q < TOPK; q++)
            out[(size_t)N * TOPK + t * TOPK + q] = sw[q] * tinv;
    }

    // overwrite own row with normalized probs (only this thread read it -> no sync needed)
#pragma unroll
    for (int i = 0; i < 32; i++)
        *reinterpret_cast<float2*>(&sh.t[tid][2 * i]) =
            make_float2(v[2 * i] * invd, v[2 * i + 1] * invd);
    __syncthreads();

    // per-expert block sums: conflict-free column reads, 2 threads per expert
    {
        int e  = tid & 63;
        int h2 = tid >> 6;
        float s0 = 0.f, s1 = 0.f, s2 = 0.f, s3 = 0.f;
#pragma unroll
        for (int r = 0; r < 64; r += 4) {
            s0 += sh.t[64 * h2 + r][e];
            s1 += sh.t[64 * h2 + r + 1][e];
            s2 += sh.t[64 * h2 + r + 2][e];
            s3 += sh.t[64 * h2 + r + 3][e];
        }
        atomicAdd(&g_ssum[e], (s0 + s1) + (s2 + s3));
    }
    if (tid < NEXP) atomicAdd(&g_cnt[tid], Hsh[tid]);

    // -------- last-block ticket: aux loss + reset globals for graph replay
    __threadfence();
    __syncthreads();
    if (tid == 0) s_last = atomicAdd(&g_done, 1u);
    __syncthreads();
    if (s_last == gridDim.x - 1) {
        float* red = &sh.t[0][0];
        if (tid < NEXP) {
            float    ssum = atomicAdd(&g_ssum[tid], 0.0f);   // L2-coherent read
            unsigned cnt  = atomicAdd(&g_cnt[tid], 0u);
            float Pi = ssum / (float)N;
            float ce = (float)cnt / ((float)N * (float)TOPK);
            red[tid] = Pi * ce * (float)NEXP;
        }
        __syncthreads();
        if (tid == 0) {
            float s = 0.f;
            for (int j = 0; j < NEXP; j++) s += red[j];
            out[(size_t)N * TOPK * 2] = s * 1e-3f;           // ALPHA
        }
        if (tid < NEXP) { g_ssum[tid] = 0.f; g_cnt[tid] = 0u; }
        if (tid == 0) g_done = 0u;
    }
}

extern "C" void kernel_launch(void* const* d_in, const int* in_sizes, int n_in,
                              void* d_out, int out_size)
{
    const float* X = (const float*)d_in[0];   // (64,4096,128) fp32 -> (N,128)
    const float* W = (const float*)d_in[1];   // (64,128) fp32
    float* out = (float*)d_out;
    int N = in_sizes[0] / HID;                // 262144

    gate_kernel<<<N / TPB, TPB>>>(X, W, out, N);
}